// round 6
// baseline (speedup 1.0000x reference)
#include <cuda_runtime.h>

// ----------------------------------------------------------------------------
// Tropical (max-plus) ViT, fp32.  C[m,n] = max_k (A[m,k]+B[n,k]) everywhere.
// Round 5: A-tile row-major (broadcast LDS, conflict-free STS.128), rowmax via
// producer atomicMax (ordered uint) -> all followers single-pass, epilogue
// subtracts row-norm scalar.
// ----------------------------------------------------------------------------

#define NEG_INF (-3.0e38f)
#define BB     8
#define NPATCH 196
#define DD     128
#define DFF    256
#define NPAD   224
#define MTOT   1568
#define NCLS   1000

__device__ float g_h   [MTOT * DD];
__device__ float g_q   [2][MTOT * DD];
__device__ float g_k   [2][MTOT * DD];
__device__ float g_vT  [2][BB * DD * NPAD];      // [b][d][j], j-pads stay 0
__device__ float g_s   [2][BB * NPATCH * NPAD];  // [b][i][j], j-pads = -inf
__device__ float g_p   [4][MTOT * DD];           // split-K parts
__device__ float g_h1  [2][MTOT * DFF];
__device__ float g_pool[BB * DD];
__device__ unsigned g_rmAtom[5][MTOT];           // ordered-uint rowmax accum
__device__ float g_rmH [MTOT];                   // rowmax(h), plain float

enum { M_EMBED, M_QKV, M_SCORES, M_ATT, M_FF1, M_FF2 };

__device__ __forceinline__ unsigned f2ord(float f) {
    unsigned u = __float_as_uint(f);
    return u ^ ((unsigned)((int)u >> 31) | 0x80000000u);
}
__device__ __forceinline__ float ord2f(unsigned u) {
    unsigned v = (u & 0x80000000u) ? (u ^ 0x80000000u) : ~u;
    return __uint_as_float(v);
}
__device__ __forceinline__ float4 f4max(float4 a, float4 b) {
    a.x = fmaxf(a.x, b.x); a.y = fmaxf(a.y, b.y);
    a.z = fmaxf(a.z, b.z); a.w = fmaxf(a.w, b.w);
    return a;
}

// ---------------------------------------------------------------------------
// Tropical NT GEMM: 32x32 tile, 128 threads, 2x4/thread, K<=64 per block.
// As row-major [m][k] (STS.128 + broadcast LDS.128); Bs k-major [k][n].
// ---------------------------------------------------------------------------
template<int MODE>
__global__ __launch_bounds__(128) void tg(
    const float* __restrict__ A, const float* __restrict__ A2,
    const float* __restrict__ B, const float* __restrict__ B2,
    const float* __restrict__ B3,
    float* __restrict__ C0, float* __restrict__ C1,
    float* __restrict__ C2, float* __restrict__ C3,
    const float* __restrict__ rmSub, unsigned* __restrict__ rmAtom,
    int M, int N, int K, int ldc,
    int aBatch, int bBatch, int cBatch,
    int splitShift, const float* __restrict__ aux)
{
    __shared__ __align__(16) float As[32][68];   // row-major, 272B rows
    __shared__ __align__(16) float Bs[64][36];   // k-major, 144B rows

    const int t  = threadIdx.x;
    const int tx = t & 7;
    const int ty = t >> 3;            // 0..15
    const int lk = tx << 2;
    const int bm = blockIdx.y << 5;
    const int bn = blockIdx.x << 5;

    const int z      = blockIdx.z;
    const int half   = z & ((1 << splitShift) - 1);
    const int batch  = z >> splitShift;
    const int kBegin = half << 6;
    const int nk     = min(K - kBegin, 64);

    const bool dualA = (MODE == M_SCORES || MODE == M_ATT || MODE == M_FF2);
    const bool dualB = (MODE == M_SCORES || MODE == M_ATT);
    const long dA = dualA ? (A2 - A) : 0;
    const long dB = dualB ? (B2 - B) : 0;
    const float tauv = (MODE == M_FF2) ? aux[0] : 0.f;

    const float* Ab = A + (long)batch * aBatch;
    const float* Bb = B + (long)batch * bBatch;

    const float* arow[2];
#pragma unroll
    for (int h = 0; h < 2; ++h) {
        int ra = bm + ty + 16 * h; if (ra > M - 1) ra = M - 1;
        if (MODE == M_EMBED) {
            int b = ra / NPATCH, np = ra % NPATCH;
            arow[h] = A + ((long)(b * 224 + (np / 14) * 16)) * 224 + (np % 14) * 16;
        } else {
            arow[h] = Ab + (long)ra * K;
        }
    }
    const float* brow[2];
#pragma unroll
    for (int h = 0; h < 2; ++h) {
        int rb = bn + ty + 16 * h; if (rb > N - 1) rb = N - 1;
        if (MODE == M_QKV) {
            const float* Bp = rb < 128 ? B : (rb < 256 ? B2 : B3);
            brow[h] = Bp + (long)(rb & 127) * K;
        } else {
            brow[h] = Bb + (long)rb * K;
        }
    }

    // ---- load all k-chunks up-front, single barrier ----
    float4 la[2][2], lb[2][2];
#pragma unroll
    for (int c = 0; c < 2; ++c) {
        if (32 * c >= nk) break;
        const int kk = kBegin + 32 * c + lk;
#pragma unroll
        for (int h = 0; h < 2; ++h) {
            float4 va;
            if (MODE == M_EMBED) {
                va = *(const float4*)(arow[h] + (kk >> 4) * 224 + (kk & 15));
            } else {
                va = *(const float4*)(arow[h] + kk);
                if (dualA)
                    va = f4max(va, *(const float4*)(arow[h] + dA + kk));
                if (MODE == M_FF2) {
                    va.x = fmaxf(va.x, tauv); va.y = fmaxf(va.y, tauv);
                    va.z = fmaxf(va.z, tauv); va.w = fmaxf(va.w, tauv);
                }
            }
            la[c][h] = va;
            float4 vb = *(const float4*)(brow[h] + kk);
            if (dualB)
                vb = f4max(vb, *(const float4*)(brow[h] + dB + kk));
            lb[c][h] = vb;
        }
    }
#pragma unroll
    for (int c = 0; c < 2; ++c) {
        if (32 * c >= nk) break;
#pragma unroll
        for (int h = 0; h < 2; ++h) {
            int r = ty + 16 * h;
            // A: straight vector store (row-major)
            *(float4*)&As[r][32 * c + lk] = la[c][h];
            // B: transpose store (k-major)
            Bs[32 * c + lk + 0][r] = lb[c][h].x;
            Bs[32 * c + lk + 1][r] = lb[c][h].y;
            Bs[32 * c + lk + 2][r] = lb[c][h].z;
            Bs[32 * c + lk + 3][r] = lb[c][h].w;
        }
    }
    __syncthreads();

    // ---- compute ----
    float acc[2][4];
#pragma unroll
    for (int i = 0; i < 2; ++i)
#pragma unroll
        for (int j = 0; j < 4; ++j) acc[i][j] = NEG_INF;

    const float* Asr0 = &As[2 * ty][0];
    const float* Asr1 = &As[2 * ty + 1][0];

#pragma unroll 4
    for (int k = 0; k < nk; k += 4) {
        float4 a0 = *(const float4*)(Asr0 + k);   // broadcast within warp
        float4 a1 = *(const float4*)(Asr1 + k);
#pragma unroll
        for (int kk = 0; kk < 4; ++kk) {
            float4 b = *(const float4*)&Bs[k + kk][lk];
            float x0 = (&a0.x)[kk], x1 = (&a1.x)[kk];
            acc[0][0] = fmaxf(acc[0][0], x0 + b.x);
            acc[0][1] = fmaxf(acc[0][1], x0 + b.y);
            acc[0][2] = fmaxf(acc[0][2], x0 + b.z);
            acc[0][3] = fmaxf(acc[0][3], x0 + b.w);
            acc[1][0] = fmaxf(acc[1][0], x1 + b.x);
            acc[1][1] = fmaxf(acc[1][1], x1 + b.y);
            acc[1][2] = fmaxf(acc[1][2], x1 + b.z);
            acc[1][3] = fmaxf(acc[1][3], x1 + b.w);
        }
    }

    // ---- epilogue ----
    const bool atomicMode = (MODE == M_EMBED || MODE == M_ATT || MODE == M_FF2);
    float* Cs[4] = { C0, C1, C2, C3 };
    float* Ch = Cs[half] + (long)batch * cBatch;

    float rsub[2] = { 0.f, 0.f };
    if (MODE == M_QKV || MODE == M_FF1) {
#pragma unroll
        for (int i = 0; i < 2; ++i) rsub[i] = rmSub[bm + 2 * ty + i];
    }

    float rmax2[2] = { NEG_INF, NEG_INF };
#pragma unroll
    for (int i = 0; i < 2; ++i) {
        int m = bm + 2 * ty + i;
        bool ok = (m < M);
#pragma unroll
        for (int j = 0; j < 4; ++j) {
            int n = bn + lk + j;
            float v = acc[i][j];
            if (MODE == M_EMBED) v += aux[(m % NPATCH) * DD + n];
            if (MODE == M_QKV || MODE == M_FF1) v -= rsub[i];
            if (atomicMode) rmax2[i] = fmaxf(rmax2[i], v);
            if (!ok) continue;
            if (MODE == M_QKV) {
                if (n < DD)
                    (C0 + (long)half * (MTOT * DD))[(long)m * DD + n] = v;
                else if (n < 2 * DD)
                    (C1 + (long)half * (MTOT * DD))[(long)m * DD + (n - DD)] = v;
                else {
                    int b = m / NPATCH, ii = m % NPATCH;
                    (C2 + (long)half * (BB * DD * NPAD))
                        [((long)b * DD + (n - 2 * DD)) * NPAD + ii] = v;
                }
            } else if (MODE == M_SCORES) {
                Ch[(long)m * ldc + n] = (n < N) ? v : NEG_INF;
            } else {
                Ch[(long)m * ldc + n] = v;
            }
        }
    }

    if (atomicMode) {
#pragma unroll
        for (int i = 0; i < 2; ++i) {
            float rm = rmax2[i];
#pragma unroll
            for (int o = 1; o < 8; o <<= 1)
                rm = fmaxf(rm, __shfl_xor_sync(0xffffffffu, rm, o));
            int m = bm + 2 * ty + i;
            if (tx == 0 && m < M) {
                int row = (MODE == M_ATT) ? batch * NPATCH + m : m;
                atomicMax(&rmAtom[row], f2ord(rm));
            }
        }
    }
}

// h = max4(parts);  rmH = decode(rmE)    (single pass, no reductions)
__global__ void combine4_k(const float* __restrict__ p0, const float* __restrict__ p1,
                           const float* __restrict__ p2, const float* __restrict__ p3,
                           const unsigned* __restrict__ rmSrc,
                           float* __restrict__ h, float* __restrict__ rmH)
{
    int r = blockIdx.x, t = threadIdx.x;
    long idx = (long)r * DD + t;
    h[idx] = fmaxf(fmaxf(p0[idx], p1[idx]), fmaxf(p2[idx], p3[idx]));
    if (t == 0) rmH[r] = ord2f(rmSrc[r]);
}

// h = max(h, max4(parts) - rmA[r]);  rmH = max(rmH, 0)
__global__ void resid4_k(const float* __restrict__ p0, const float* __restrict__ p1,
                         const float* __restrict__ p2, const float* __restrict__ p3,
                         const unsigned* __restrict__ rmA,
                         float* __restrict__ h, float* __restrict__ rmH)
{
    int r = blockIdx.x, t = threadIdx.x;
    long idx = (long)r * DD + t;
    float av = fmaxf(fmaxf(p0[idx], p1[idx]), fmaxf(p2[idx], p3[idx]));
    float ra = ord2f(rmA[r]);
    h[idx] = fmaxf(h[idx], av - ra);
    if (t == 0) rmH[r] = fmaxf(rmH[r], 0.f);
}

__global__ void pool_k()
{
    int b = blockIdx.x, t = threadIdx.x;
    float acc = NEG_INF;
    const float* base = g_h + (long)b * NPATCH * DD + t;
#pragma unroll 4
    for (int n = 0; n < NPATCH; ++n) acc = fmaxf(acc, base[(long)n * DD]);
    g_pool[b * DD + t] = acc;
}

__global__ void head_k(const float* __restrict__ W, const float* __restrict__ ls,
                       float* __restrict__ out)
{
    __shared__ float p[DD];
    int b = blockIdx.y, t = threadIdx.x;
    p[t] = g_pool[b * DD + t];
    __syncthreads();
    int c = blockIdx.x * 128 + t;
    if (c < NCLS) {
        float acc = NEG_INF;
        const float* w = W + (long)c * DD;
#pragma unroll 4
        for (int d = 0; d < DD; ++d) acc = fmaxf(acc, p[d] + w[d]);
        out[(long)b * NCLS + c] = acc * ls[0];
    }
}

// ---------------------------------------------------------------------------

extern "C" void kernel_launch(void* const* d_in, const int* in_sizes, int n_in,
                              void* d_out, int out_size)
{
    (void)in_sizes; (void)n_in; (void)out_size;
    const float* x       = (const float*)d_in[0];
    const float* embed_W = (const float*)d_in[1];
    const float* pos     = (const float*)d_in[2];
    const float* head_W  = (const float*)d_in[15];
    const float* lscale  = (const float*)d_in[16];
    float* out = (float*)d_out;

    float *h, *q, *k, *vT, *s, *p, *h1, *rmH;
    unsigned* rmA;
    cudaGetSymbolAddress((void**)&h,   g_h);
    cudaGetSymbolAddress((void**)&q,   g_q);
    cudaGetSymbolAddress((void**)&k,   g_k);
    cudaGetSymbolAddress((void**)&vT,  g_vT);
    cudaGetSymbolAddress((void**)&s,   g_s);
    cudaGetSymbolAddress((void**)&p,   g_p);
    cudaGetSymbolAddress((void**)&h1,  g_h1);
    cudaGetSymbolAddress((void**)&rmA, g_rmAtom);
    cudaGetSymbolAddress((void**)&rmH, g_rmH);

    float *q1 = q + MTOT * DD, *k1 = k + MTOT * DD;
    float *vT1 = vT + BB * DD * NPAD, *s1 = s + BB * NPATCH * NPAD;
    float *p1 = p + MTOT * DD, *p2 = p + 2 * MTOT * DD, *p3 = p + 3 * MTOT * DD;
    float *h11 = h1 + MTOT * DFF;
    unsigned *rmE = rmA;                  // [0] embed
    // per-layer atomic rows: [1+2l] = attn, [2+2l] = ff

    // reset all atomic rowmax accumulators (ordered-uint 0 == -inf)
    cudaMemsetAsync(rmA, 0, 5 * MTOT * sizeof(unsigned));

    // embed: patchify fused, K=256 split4 -> parts; +pos & rowmax in epilogue
    tg<M_EMBED><<<dim3(4, 49, 4), 128>>>(x, 0, embed_W, 0, 0, p, p1, p2, p3,
        0, rmE, MTOT, DD, 256, DD, 0, 0, 0, 2, pos);
    combine4_k<<<MTOT, 128>>>(p, p1, p2, p3, rmE, h, rmH);

    for (int l = 0; l < 2; ++l) {
        const float* qW  = (const float*)d_in[3 + 6 * l];
        const float* kW  = (const float*)d_in[4 + 6 * l];
        const float* vW  = (const float*)d_in[5 + 6 * l];
        const float* f1W = (const float*)d_in[6 + 6 * l];
        const float* f2W = (const float*)d_in[7 + 6 * l];
        const float* tau = (const float*)d_in[8 + 6 * l];
        unsigned* rmAt = rmA + (1 + 2 * l) * MTOT;
        unsigned* rmFf = rmA + (2 + 2 * l) * MTOT;

        // q/k/v fused: A=h, epilogue subtracts rmH; K=128 split2
        tg<M_QKV><<<dim3(12, 49, 2), 128>>>(h, 0, qW, kW, vW, q, k, vT, 0,
            rmH, 0, MTOT, 384, DD, 0, 0, 0, 0, 1, 0);

        // scores: A=max(q0,q1), B=max(k0,k1); K=128 split2 -> s halves
        tg<M_SCORES><<<dim3(7, 7, 16), 128>>>(q, q1, k, k1, 0, s, s1, 0, 0,
            0, 0, NPATCH, NPATCH, DD, NPAD,
            NPATCH * DD, NPATCH * DD, NPATCH * NPAD, 1, 0);

        // attn out: A=max(s0,s1), B=max(vT0,vT1); K=224 split4 -> parts + rowmax
        tg<M_ATT><<<dim3(4, 7, 32), 128>>>(s, s1, vT, vT1, 0, p, p1, p2, p3,
            0, rmAt, NPATCH, DD, NPAD, DD,
            NPATCH * NPAD, DD * NPAD, NPATCH * DD, 2, 0);
        resid4_k<<<MTOT, 128>>>(p, p1, p2, p3, rmAt, h, rmH);

        // ff1: A=h, epilogue subtracts rmH; K=128 split2 -> h1 halves
        tg<M_FF1><<<dim3(8, 49, 2), 128>>>(h, 0, f1W, 0, 0, h1, h11, 0, 0,
            rmH, 0, MTOT, DFF, DD, DFF, 0, 0, 0, 1, 0);

        // ff2: A=max(h1a,h1b,tau); K=256 split4 -> parts + rowmax
        tg<M_FF2><<<dim3(4, 49, 4), 128>>>(h1, h11, f2W, 0, 0, p, p1, p2, p3,
            0, rmFf, MTOT, DD, DFF, DD, 0, 0, 0, 2, tau);
        resid4_k<<<MTOT, 128>>>(p, p1, p2, p3, rmFf, h, rmH);
    }

    pool_k<<<BB, 128>>>();
    head_k<<<dim3(8, BB), 128>>>(head_W, lscale, out);
}